// round 1
// baseline (speedup 1.0000x reference)
#include <cuda_runtime.h>

// Problem constants
#define BDIM   2
#define CDIM   512
#define FDIM   16
#define HWDIM  1024                 // h*w = 32*32
#define MROWS  (BDIM*FDIM*HWDIM)    // 32768 rows; r = b*16384 + f*1024 + hw
#define NQKV   (3*CDIM)             // 1536
#define HEADS  8
#define DHEAD  64
#define ATTN_SCALE 0.125f           // 64^-0.5

// Scratch (static device arrays: allocation-free per harness rules)
__device__ float g_qkv[(size_t)MROWS * NQKV];   // ~201 MB
__device__ float g_ao [(size_t)MROWS * CDIM];   // ~67 MB

// ---------------- f32x2 packed-FMA helpers (Blackwell) ----------------
__device__ __forceinline__ unsigned long long dup2(float v) {
    unsigned long long r;
    asm("mov.b64 %0, {%1, %1};" : "=l"(r) : "f"(v));
    return r;
}
__device__ __forceinline__ void fma2(unsigned long long& d,
                                     unsigned long long a,
                                     unsigned long long b) {
    asm("fma.rn.f32x2 %0, %1, %2, %0;" : "+l"(d) : "l"(a), "l"(b));
}

// =======================================================================
// Phase 1: qkv = gather-transpose(x) @ w_qkv
//   A[r][c] = x[((b*512 + c)*16 + f)*1024 + hw],  r = b*16384 + f*1024 + hw
//   B = w_qkv (512 x 1536) row-major
//   C = g_qkv (32768 x 1536) row-major
// Tiles: BM=BN=128, BK=16, 256 threads, 8x8 microtile (n packed in f32x2 pairs)
// =======================================================================
__global__ __launch_bounds__(256, 2)
void qkv_gemm(const float* __restrict__ gx, const float* __restrict__ wqkv) {
    __shared__ float As[16 * 128];
    __shared__ float Bs[16 * 128];

    const int t   = threadIdx.x;
    const int tx  = t & 15;        // n-dim thread coord
    const int ty  = t >> 4;        // m-dim thread coord
    const int col0 = blockIdx.x * 128;
    const int row0 = blockIdx.y * 128;
    const int b    = row0 >> 14;
    const int f    = (row0 >> 10) & 15;
    const int hw0  = row0 & 1023;

    const int lm = t & 127;        // load lane (m for A, n for B)
    const int lk = t >> 7;         // load k-half

    // A base: x element for c=0 at this (b, f, hw0+lm); c stride = 16*1024
    const float* xbase = gx + ((size_t)b * CDIM * FDIM + f) * HWDIM + hw0 + lm;

    unsigned long long acc[8][4];
    #pragma unroll
    for (int i = 0; i < 8; i++)
        #pragma unroll
        for (int p = 0; p < 4; p++) acc[i][p] = 0ULL;

    for (int kt = 0; kt < CDIM; kt += 16) {
        #pragma unroll
        for (int u = 0; u < 8; u++) {
            int k = lk * 8 + u;
            As[k * 128 + lm] = xbase[(size_t)(kt + k) * (FDIM * HWDIM)];
        }
        #pragma unroll
        for (int u = 0; u < 8; u++) {
            int k = lk * 8 + u;
            Bs[k * 128 + lm] = wqkv[(size_t)(kt + k) * NQKV + col0 + lm];
        }
        __syncthreads();

        #pragma unroll
        for (int k = 0; k < 16; k++) {
            float a[8];
            *(float4*)&a[0] = *(const float4*)&As[k * 128 + ty * 8];
            *(float4*)&a[4] = *(const float4*)&As[k * 128 + ty * 8 + 4];
            unsigned long long bp[4];
            #pragma unroll
            for (int p = 0; p < 4; p++)
                bp[p] = *(const unsigned long long*)&Bs[k * 128 + tx * 8 + 2 * p];
            #pragma unroll
            for (int i = 0; i < 8; i++) {
                unsigned long long ad = dup2(a[i]);
                #pragma unroll
                for (int p = 0; p < 4; p++) fma2(acc[i][p], ad, bp[p]);
            }
        }
        __syncthreads();
    }

    // Epilogue: vectorized row-major stores (two STG.128 per row)
    #pragma unroll
    for (int i = 0; i < 8; i++) {
        size_t m = (size_t)row0 + ty * 8 + i;
        float* cptr = g_qkv + m * NQKV + col0 + tx * 8;
        ulonglong2 v0; v0.x = acc[i][0]; v0.y = acc[i][1];
        ulonglong2 v1; v1.x = acc[i][2]; v1.y = acc[i][3];
        *(ulonglong2*)(cptr)     = v0;
        *(ulonglong2*)(cptr + 4) = v1;
    }
}

// =======================================================================
// Phase 2: per (sequence, head) attention.
//   One CTA of 128 threads per (b, hw, head). seq len = 16, d = 64.
// =======================================================================
__global__ __launch_bounds__(128)
void attn_kernel(const float* __restrict__ pos_bias) {
    __shared__ float qs[16 * 65];
    __shared__ float ks[16 * 65];
    __shared__ float vs[16 * 65];
    __shared__ float sim[16 * 17];

    const int t    = threadIdx.x;
    const int bid  = blockIdx.x;
    const int head = bid & 7;
    const int hw   = (bid >> 3) & 1023;
    const int b    = bid >> 13;

    // row r(f) = b*16384 + f*1024 + hw ; row pitch NQKV
    const size_t seqbase = ((size_t)b * 16384 + hw) * NQKV + head * DHEAD;

    #pragma unroll
    for (int it = 0; it < 8; it++) {
        int idx = t + it * 128;
        int fi = idx >> 6, d = idx & 63;
        size_t g = seqbase + (size_t)fi * (1024 * (size_t)NQKV) + d;
        qs[fi * 65 + d] = g_qkv[g] * ATTN_SCALE;
        ks[fi * 65 + d] = g_qkv[g + CDIM];
        vs[fi * 65 + d] = g_qkv[g + 2 * CDIM];
    }
    __syncthreads();

    #pragma unroll
    for (int e = t; e < 256; e += 128) {
        int i = e >> 4, j = e & 15;
        float s = 0.f;
        #pragma unroll
        for (int d = 0; d < 64; d++) s += qs[i * 65 + d] * ks[j * 65 + d];
        sim[i * 17 + j] = s + pos_bias[head * 256 + i * 16 + j];
    }
    __syncthreads();

    if (t < 16) {
        const int i = t;
        float mx = -1e30f;
        #pragma unroll
        for (int j = 0; j < 16; j++) mx = fmaxf(mx, sim[i * 17 + j]);
        float e[16], sum = 0.f;
        #pragma unroll
        for (int j = 0; j < 16; j++) { e[j] = __expf(sim[i * 17 + j] - mx); sum += e[j]; }
        float inv = 1.0f / sum;
        #pragma unroll
        for (int j = 0; j < 16; j++) sim[i * 17 + j] = e[j] * inv;
    }
    __syncthreads();

    #pragma unroll
    for (int it = 0; it < 8; it++) {
        int idx = t + it * 128;
        int i = idx >> 6, d = idx & 63;
        float s = 0.f;
        #pragma unroll
        for (int j = 0; j < 16; j++) s += sim[i * 17 + j] * vs[j * 65 + d];
        g_ao[((size_t)b * 16384 + (size_t)i * 1024 + hw) * CDIM + head * DHEAD + d] = s;
    }
}

// =======================================================================
// Phase 3: out = g_ao @ w_out, written directly in (b, c, f, h, w) layout.
//   A = g_ao (32768 x 512) row-major; B = w_out (512 x 512) row-major
//   C[r][n] -> out[((b*512 + n)*16 + f)*1024 + hw]
// =======================================================================
__global__ __launch_bounds__(256, 2)
void out_gemm(const float* __restrict__ wout, float* __restrict__ gout) {
    __shared__ float As[16 * 128];
    __shared__ float Bs[16 * 128];

    const int t   = threadIdx.x;
    const int tx  = t & 15;
    const int ty  = t >> 4;
    const int col0 = blockIdx.x * 128;
    const int row0 = blockIdx.y * 128;
    const int b    = row0 >> 14;
    const int f    = (row0 >> 10) & 15;
    const int hw0  = row0 & 1023;

    const int lkq = t & 3;     // A-load: which float4 in k
    const int lmr = t >> 2;    // A-load: row 0..63
    const int ln  = t & 127;   // B-load n
    const int lkh = t >> 7;    // B-load k-half

    unsigned long long acc[8][4];
    #pragma unroll
    for (int i = 0; i < 8; i++)
        #pragma unroll
        for (int p = 0; p < 4; p++) acc[i][p] = 0ULL;

    for (int kt = 0; kt < CDIM; kt += 16) {
        #pragma unroll
        for (int v = 0; v < 2; v++) {
            int m = lmr + v * 64;
            float4 a4 = *(const float4*)&g_ao[(size_t)(row0 + m) * CDIM + kt + lkq * 4];
            As[(lkq * 4 + 0) * 128 + m] = a4.x;
            As[(lkq * 4 + 1) * 128 + m] = a4.y;
            As[(lkq * 4 + 2) * 128 + m] = a4.z;
            As[(lkq * 4 + 3) * 128 + m] = a4.w;
        }
        #pragma unroll
        for (int u = 0; u < 8; u++) {
            int k = lkh * 8 + u;
            Bs[k * 128 + ln] = wout[(size_t)(kt + k) * CDIM + col0 + ln];
        }
        __syncthreads();

        #pragma unroll
        for (int k = 0; k < 16; k++) {
            float a[8];
            *(float4*)&a[0] = *(const float4*)&As[k * 128 + ty * 8];
            *(float4*)&a[4] = *(const float4*)&As[k * 128 + ty * 8 + 4];
            unsigned long long bp[4];
            #pragma unroll
            for (int p = 0; p < 4; p++)
                bp[p] = *(const unsigned long long*)&Bs[k * 128 + tx * 8 + 2 * p];
            #pragma unroll
            for (int i = 0; i < 8; i++) {
                unsigned long long ad = dup2(a[i]);
                #pragma unroll
                for (int p = 0; p < 4; p++) fma2(acc[i][p], ad, bp[p]);
            }
        }
        __syncthreads();
    }

    // Epilogue: scatter into (b, c, f, h, w). n-dim is far-strided here
    // (stride 16384 floats), so writes are scalar; m (=hw) is thread-local.
    #pragma unroll
    for (int i = 0; i < 8; i++) {
        int mloc = ty * 8 + i;
        #pragma unroll
        for (int p = 0; p < 4; p++) {
            float2 c = *reinterpret_cast<float2*>(&acc[i][p]);
            int n0 = col0 + tx * 8 + 2 * p;
            gout[((size_t)(b * CDIM + n0)     * FDIM + f) * HWDIM + hw0 + mloc] = c.x;
            gout[((size_t)(b * CDIM + n0 + 1) * FDIM + f) * HWDIM + hw0 + mloc] = c.y;
        }
    }
}

extern "C" void kernel_launch(void* const* d_in, const int* in_sizes, int n_in,
                              void* d_out, int out_size) {
    const float* x        = (const float*)d_in[0];
    const float* pos_bias = (const float*)d_in[1];
    const float* w_qkv    = (const float*)d_in[2];
    const float* w_out    = (const float*)d_in[3];
    float* out = (float*)d_out;

    dim3 g1(NQKV / 128, MROWS / 128);   // (12, 256)
    qkv_gemm<<<g1, 256>>>(x, w_qkv);

    attn_kernel<<<BDIM * HWDIM * HEADS, 128>>>(pos_bias);   // 16384 blocks

    dim3 g3(CDIM / 128, MROWS / 128);   // (4, 256)
    out_gemm<<<g3, 256>>>(w_out, out);
}

// round 3
// speedup vs baseline: 2.5758x; 2.5758x over previous
#include <cuda_runtime.h>
#include <cuda_bf16.h>
#include <cstdint>

// -------- problem constants --------
#define BDIM   2
#define CDIM   512
#define FDIM   16
#define HWDIM  1024
#define MROWS  32768            // r = b*16384 + f*1024 + hw
#define NQKV   1536
#define HEADS  8
#define DHEAD  64
#define ATTN_SCALE 0.125f

#define KP      1536            // expanded K' = 3*512 (hi*hi | lo*hi | hi*lo)
#define NCHUNK  24              // K'/64
#define STAGE_BYTES 32768       // A 16KB + B 16KB
#define SMEM_DYN (3*STAGE_BYTES)

// -------- scratch (__device__ globals: allocation-free) --------
__device__ float         g_qkv[(size_t)MROWS * NQKV];
__device__ __nv_bfloat16 g_a1 [(size_t)MROWS * 1024];   // x transposed, [hi|lo]
__device__ __nv_bfloat16 g_ao [(size_t)MROWS * 1024];   // attention out, [hi|lo]
__device__ __nv_bfloat16 g_b1 [(size_t)NQKV  * KP];     // w_qkv^T [hi|hi|lo]
__device__ __nv_bfloat16 g_b3 [(size_t)CDIM  * KP];     // w_out^T [hi|hi|lo]

// ==================== helpers ====================
__device__ __forceinline__ uint32_t smem_u32(const void* p) {
    uint32_t a;
    asm("{ .reg .u64 t; cvta.to.shared.u64 t, %1; cvt.u32.u64 %0, t; }" : "=r"(a) : "l"(p));
    return a;
}
__device__ __forceinline__ void cpa16(uint32_t dst, const void* src) {
    asm volatile("cp.async.cg.shared.global [%0], [%1], 16;" :: "r"(dst), "l"(src) : "memory");
}
__device__ __forceinline__ void cpa_commit() { asm volatile("cp.async.commit_group;" ::: "memory"); }
__device__ __forceinline__ void cpa_wait1()  { asm volatile("cp.async.wait_group 1;" ::: "memory"); }

__device__ __forceinline__ uint32_t sw_addr(uint32_t base, int row, int seg) {
    uint32_t off = (uint32_t)(row * 128 + seg * 16);
    return base + (off ^ ((off >> 3) & 0x70));
}
__device__ __forceinline__ void ldsm4(uint32_t& r0, uint32_t& r1, uint32_t& r2, uint32_t& r3,
                                      uint32_t addr) {
    asm volatile("ldmatrix.sync.aligned.m8n8.x4.shared.b16 {%0,%1,%2,%3}, [%4];"
                 : "=r"(r0), "=r"(r1), "=r"(r2), "=r"(r3) : "r"(addr));
}
__device__ __forceinline__ void mma16816(float& d0, float& d1, float& d2, float& d3,
                                         uint32_t a0, uint32_t a1, uint32_t a2, uint32_t a3,
                                         uint32_t b0, uint32_t b1) {
    asm volatile(
        "mma.sync.aligned.m16n8k16.row.col.f32.bf16.bf16.f32 "
        "{%0,%1,%2,%3},{%4,%5,%6,%7},{%8,%9},{%0,%1,%2,%3};"
        : "+f"(d0), "+f"(d1), "+f"(d2), "+f"(d3)
        : "r"(a0), "r"(a1), "r"(a2), "r"(a3), "r"(b0), "r"(b1));
}
__device__ __forceinline__ void bf16_split(float v, __nv_bfloat16& h, __nv_bfloat16& l) {
    h = __float2bfloat16(v);
    l = __float2bfloat16(v - __bfloat162float(h));
}

// 128-row x 128B tile -> SW128 smem, 256 threads
__device__ __forceinline__ void load_tile256(uint32_t smbase, const char* g, size_t pitch, int t) {
    #pragma unroll
    for (int i = 0; i < 4; i++) {
        int id = t + i * 256;
        int row = id >> 3, seg = id & 7;
        uint32_t off = (uint32_t)(row * 128 + seg * 16);
        cpa16(smbase + (off ^ ((off >> 3) & 0x70)), g + (size_t)row * pitch + seg * 16);
    }
}

// warp computes a 64(m) x 32(n) x 64(k) contribution from one stage
__device__ __forceinline__ void compute_chunk(uint32_t aBase, uint32_t bBase,
                                              int lane, int wm, int wn,
                                              float acc[4][4][4]) {
    const int a_row = wm + (lane & 15);
    const int a_sh  = lane >> 4;
    const int b_row = wn + (lane & 7) + ((lane >> 4) & 1) * 8;
    const int b_sh  = (lane >> 3) & 1;
    #pragma unroll
    for (int ks = 0; ks < 4; ks++) {
        uint32_t af[4][4];
        #pragma unroll
        for (int mi = 0; mi < 4; mi++)
            ldsm4(af[mi][0], af[mi][1], af[mi][2], af[mi][3],
                  sw_addr(aBase, a_row + mi * 16, ks * 2 + a_sh));
        uint32_t bf[2][4];
        #pragma unroll
        for (int g = 0; g < 2; g++)
            ldsm4(bf[g][0], bf[g][1], bf[g][2], bf[g][3],
                  sw_addr(bBase, b_row + g * 16, ks * 2 + b_sh));
        #pragma unroll
        for (int mi = 0; mi < 4; mi++)
            #pragma unroll
            for (int nj = 0; nj < 4; nj++)
                mma16816(acc[mi][nj][0], acc[mi][nj][1], acc[mi][nj][2], acc[mi][nj][3],
                         af[mi][0], af[mi][1], af[mi][2], af[mi][3],
                         bf[nj >> 1][(nj & 1) * 2], bf[nj >> 1][(nj & 1) * 2 + 1]);
    }
}

#define GEMM_MAINLOOP(ABASE, BBASE)                                                        \
    float acc[4][4][4];                                                                    \
    _Pragma("unroll")                                                                      \
    for (int mi = 0; mi < 4; mi++)                                                         \
        _Pragma("unroll")                                                                  \
        for (int nj = 0; nj < 4; nj++)                                                     \
            _Pragma("unroll")                                                              \
            for (int q = 0; q < 4; q++) acc[mi][nj][q] = 0.f;                              \
    const int wid = t >> 5, lane = t & 31;                                                 \
    const int wm = (wid & 1) * 64, wn = (wid >> 1) * 32;                                   \
    _Pragma("unroll")                                                                      \
    for (int c = 0; c < 2; c++) {                                                          \
        load_tile256(dbase + c * STAGE_BYTES,         (const char*)(ABASE) + (size_t)(c * 64) * 2, 2048, t);   \
        load_tile256(dbase + c * STAGE_BYTES + 16384, (const char*)(BBASE) + (size_t)(c * 64) * 2, KP * 2, t); \
        cpa_commit();                                                                      \
    }                                                                                      \
    for (int i = 0; i < NCHUNK; i++) {                                                     \
        cpa_wait1();                                                                       \
        __syncthreads();                                                                   \
        const int i2 = i + 2;                                                              \
        if (i2 < NCHUNK) {                                                                 \
            const int s2 = i2 % 3;                                                         \
            const int kc = i2 * 64;                                                        \
            const int ka = (kc < 1024) ? kc : (kc - 1024);                                 \
            load_tile256(dbase + s2 * STAGE_BYTES,         (const char*)(ABASE) + (size_t)ka * 2, 2048, t);   \
            load_tile256(dbase + s2 * STAGE_BYTES + 16384, (const char*)(BBASE) + (size_t)kc * 2, KP * 2, t); \
        }                                                                                  \
        cpa_commit();                                                                      \
        const int s = i % 3;                                                               \
        compute_chunk(dbase + s * STAGE_BYTES, dbase + s * STAGE_BYTES + 16384,            \
                      lane, wm, wn, acc);                                                  \
    }

// ==================== prep kernels ====================
__global__ __launch_bounds__(256)
void prep_a1(const float* __restrict__ x) {
    __shared__ float sm[32 * 33];
    const int tx = threadIdx.x & 31, ty = threadIdx.x >> 5;
    const int c0 = blockIdx.x * 32;
    const int hw0 = blockIdx.y * 32;
    const int b = blockIdx.z >> 4, f = blockIdx.z & 15;
    const float* xs = x + (size_t)b * (CDIM * FDIM * HWDIM) + (size_t)f * HWDIM;
    #pragma unroll
    for (int j = 0; j < 4; j++) {
        int ci = ty + 8 * j;
        sm[ci * 33 + tx] = xs[(size_t)(c0 + ci) * (FDIM * HWDIM) + hw0 + tx];
    }
    __syncthreads();
    const size_t rbase = (size_t)b * 16384 + (size_t)f * 1024 + hw0;
    #pragma unroll
    for (int j = 0; j < 4; j++) {
        int hwi = ty + 8 * j;
        float v = sm[tx * 33 + hwi];
        __nv_bfloat16 h, l; bf16_split(v, h, l);
        size_t ro = (rbase + hwi) * 1024;
        g_a1[ro + c0 + tx]       = h;
        g_a1[ro + 512 + c0 + tx] = l;
    }
}

__device__ __forceinline__ void prep_b_body(const float* __restrict__ w,
                                            __nv_bfloat16* __restrict__ bt, int nout) {
    __shared__ float sm[32 * 33];
    const int tx = threadIdx.x & 31, ty = threadIdx.x >> 5;
    const int kk0 = blockIdx.x * 32;
    const int n0  = blockIdx.y * 32;
    const int ksrc0 = kk0 & 511;
    const int seg = kk0 >> 9;
    #pragma unroll
    for (int j = 0; j < 4; j++) {
        int ki = ty + 8 * j;
        sm[ki * 33 + tx] = w[(size_t)(ksrc0 + ki) * nout + n0 + tx];
    }
    __syncthreads();
    #pragma unroll
    for (int j = 0; j < 4; j++) {
        int ni = ty + 8 * j;
        float v = sm[tx * 33 + ni];
        __nv_bfloat16 h, l; bf16_split(v, h, l);
        bt[(size_t)(n0 + ni) * KP + kk0 + tx] = (seg < 2) ? h : l;
    }
}
__global__ __launch_bounds__(256) void prep_b1(const float* __restrict__ w) { prep_b_body(w, g_b1, NQKV); }
__global__ __launch_bounds__(256) void prep_b3(const float* __restrict__ w) { prep_b_body(w, g_b3, CDIM); }

// ==================== GEMM1: qkv ====================
__global__ __launch_bounds__(256, 2)
void gemm_qkv() {
    extern __shared__ char dyn[];
    const int t = threadIdx.x;
    const int col0 = blockIdx.x * 128;
    const int row0 = blockIdx.y * 128;
    const uint32_t dbase = smem_u32(dyn);
    const __nv_bfloat16* Abase = g_a1 + (size_t)row0 * 1024;
    const __nv_bfloat16* Bbase = g_b1 + (size_t)col0 * KP;

    GEMM_MAINLOOP(Abase, Bbase)

    const int gid = lane >> 2;
    const int cid = (lane & 3) * 2;
    #pragma unroll
    for (int mi = 0; mi < 4; mi++) {
        #pragma unroll
        for (int nj = 0; nj < 4; nj++) {
            size_t r0 = (size_t)(row0 + wm + mi * 16 + gid);
            int    cc = col0 + wn + nj * 8 + cid;
            float2 v0 = make_float2(acc[mi][nj][0], acc[mi][nj][1]);
            float2 v1 = make_float2(acc[mi][nj][2], acc[mi][nj][3]);
            *(float2*)&g_qkv[r0 * NQKV + cc]       = v0;
            *(float2*)&g_qkv[(r0 + 8) * NQKV + cc] = v1;
        }
    }
}

// ==================== GEMM3: out projection ====================
__global__ __launch_bounds__(256, 2)
void gemm_out(float* __restrict__ out) {
    extern __shared__ char dyn[];
    const int t = threadIdx.x;
    const int col0 = blockIdx.x * 128;
    const int row0 = blockIdx.y * 128;
    const uint32_t dbase = smem_u32(dyn);
    const __nv_bfloat16* Abase = g_ao + (size_t)row0 * 1024;
    const __nv_bfloat16* Bbase = g_b3 + (size_t)col0 * KP;

    GEMM_MAINLOOP(Abase, Bbase)

    const int gid = lane >> 2;
    const int cid = (lane & 3) * 2;
    const int b = row0 >> 14, f = (row0 >> 10) & 15, hw0 = row0 & 1023;
    #pragma unroll
    for (int mi = 0; mi < 4; mi++) {
        #pragma unroll
        for (int nj = 0; nj < 4; nj++) {
            int m0 = hw0 + wm + mi * 16 + gid;
            int n  = col0 + wn + nj * 8 + cid;
            size_t p0 = ((size_t)(b * CDIM + n)     * FDIM + f) * HWDIM;
            size_t p1 = ((size_t)(b * CDIM + n + 1) * FDIM + f) * HWDIM;
            out[p0 + m0]     = acc[mi][nj][0];
            out[p1 + m0]     = acc[mi][nj][1];
            out[p0 + m0 + 8] = acc[mi][nj][2];
            out[p1 + m0 + 8] = acc[mi][nj][3];
        }
    }
}

// ==================== attention ====================
__global__ __launch_bounds__(128)
void attn_kernel(const float* __restrict__ pos_bias) {
    __shared__ float qs[16 * 65];
    __shared__ float ks[16 * 65];
    __shared__ float vs[16 * 65];
    __shared__ float sim[16 * 17];

    const int t = threadIdx.x;
    const int bid = blockIdx.x;
    const int head = bid & 7;
    const int hw = (bid >> 3) & 1023;
    const int b = bid >> 13;

    const size_t seqbase = ((size_t)b * 16384 + hw) * NQKV + head * DHEAD;

    #pragma unroll
    for (int it = 0; it < 8; it++) {
        int idx = t + it * 128;
        int fi = idx >> 6, d = idx & 63;
        size_t g = seqbase + (size_t)fi * (1024 * (size_t)NQKV) + d;
        qs[fi * 65 + d] = g_qkv[g] * ATTN_SCALE;
        ks[fi * 65 + d] = g_qkv[g + CDIM];
        vs[fi * 65 + d] = g_qkv[g + 2 * CDIM];
    }
    __syncthreads();

    #pragma unroll
    for (int e = t; e < 256; e += 128) {
        int i = e >> 4, j = e & 15;
        float s = 0.f;
        #pragma unroll
        for (int d = 0; d < 64; d++) s += qs[i * 65 + d] * ks[j * 65 + d];
        sim[i * 17 + j] = s + pos_bias[head * 256 + i * 16 + j];
    }
    __syncthreads();

    if (t < 16) {
        const int i = t;
        float mx = -1e30f;
        #pragma unroll
        for (int j = 0; j < 16; j++) mx = fmaxf(mx, sim[i * 17 + j]);
        float e[16], sum = 0.f;
        #pragma unroll
        for (int j = 0; j < 16; j++) { e[j] = __expf(sim[i * 17 + j] - mx); sum += e[j]; }
        float inv = 1.0f / sum;
        #pragma unroll
        for (int j = 0; j < 16; j++) sim[i * 17 + j] = e[j] * inv;
    }
    __syncthreads();

    #pragma unroll
    for (int it = 0; it < 8; it++) {
        int idx = t + it * 128;
        int i = idx >> 6, d = idx & 63;
        float s = 0.f;
        #pragma unroll
        for (int j = 0; j < 16; j++) s += sim[i * 17 + j] * vs[j * 65 + d];
        __nv_bfloat16 h, l; bf16_split(s, h, l);
        size_t ro = ((size_t)b * 16384 + (size_t)i * 1024 + hw) * 1024;
        g_ao[ro + head * DHEAD + d]       = h;
        g_ao[ro + 512 + head * DHEAD + d] = l;
    }
}

// ==================== launch ====================
extern "C" void kernel_launch(void* const* d_in, const int* in_sizes, int n_in,
                              void* d_out, int out_size) {
    const float* x        = (const float*)d_in[0];
    const float* pos_bias = (const float*)d_in[1];
    const float* w_qkv    = (const float*)d_in[2];
    const float* w_out    = (const float*)d_in[3];
    float* out = (float*)d_out;

    cudaFuncSetAttribute(gemm_qkv, cudaFuncAttributeMaxDynamicSharedMemorySize, SMEM_DYN);
    cudaFuncSetAttribute(gemm_out, cudaFuncAttributeMaxDynamicSharedMemorySize, SMEM_DYN);

    prep_a1<<<dim3(16, 32, 32), 256>>>(x);
    prep_b1<<<dim3(48, 48), 256>>>(w_qkv);
    prep_b3<<<dim3(48, 16), 256>>>(w_out);

    gemm_qkv<<<dim3(NQKV / 128, MROWS / 128), 256, SMEM_DYN>>>();

    attn_kernel<<<BDIM * HWDIM * HEADS, 128>>>(pos_bias);

    gemm_out<<<dim3(CDIM / 128, MROWS / 128), 256, SMEM_DYN>>>(out);
}